// round 1
// baseline (speedup 1.0000x reference)
#include <cuda_runtime.h>
#include <cstdint>

// Problem dims (fixed by the reference setup)
#define BATCH   8
#define NT      1024          // N*T = 32*32
#define MLANES  64            // M
#define LPTS    16            // L
#define NEMBD   128
#define EDIM    12
#define NPOS    (BATCH * NT * MLANES)   // 524288

// Scratch: edge tensor [NPOS][12] floats = 25 MB (static __device__ allowed)
__device__ float g_edge[(size_t)NPOS * EDIM];

// ---------------------------------------------------------------------------
// Kernel 1: compute edge features.
// agent: (B, NT, 8) flattened; lane: (B, M, 16, 4) flattened.
// One thread per (b, i, m). blockDim=256: 4 agent-rows per block, 64 m each.
// ---------------------------------------------------------------------------
__device__ __forceinline__ float4 dx_at(float px, float py, float ps, float pc,
                                        float flag1, float4 q) {
    // q = (lx, ly, ls, lc)
    float f2 = (q.x == 0.f && q.y == 0.f && q.z == 0.f && q.w == 0.f) ? 0.f : 1.f;
    float f  = flag1 * f2;
    float dxw = px - q.x;
    float dyw = py - q.y;
    float dX = (dxw * q.w + dyw * q.z) * 0.1f * f;   // delta_x / 10
    float dY = (-dxw * q.z + dyw * q.w) * 0.1f * f;  // delta_y / 10
    float ds = (ps * q.w - pc * q.z) * f;
    float dc = (pc * q.w + ps * q.z) * f;
    return make_float4(dX, dY, ds, dc);
}

__global__ void edge_kernel(const float* __restrict__ agent,
                            const float* __restrict__ lane) {
    int m   = threadIdx.x & 63;
    int g   = threadIdx.x >> 6;
    int row = blockIdx.x * 4 + g;          // (b*NT + i), 0..8191
    int b   = row >> 10;

    // Agent row (8 floats) — warp-uniform within each 64-thread group (broadcast)
    const float4* ap = reinterpret_cast<const float4*>(agent + (size_t)row * 8);
    float4 a0 = __ldg(ap + 0);
    float4 a1 = __ldg(ap + 1);
    float flag1 = (a0.x == 0.f && a0.y == 0.f && a0.z == 0.f && a0.w == 0.f &&
                   a1.x == 0.f && a1.y == 0.f && a1.z == 0.f && a1.w == 0.f) ? 0.f : 1.f;
    float px = a0.x, py = a0.y, ps = a0.w, pc = a1.x;

    // Lane points for this (b, m): 16 float4s, L2-resident across all i
    const float4* lp = reinterpret_cast<const float4*>(lane + ((size_t)(b * MLANES + m)) * 64);

    float bestAbs = 3.4e38f;
    int   bestl   = 0;
#pragma unroll
    for (int l = 0; l < LPTS; l++) {
        float4 q = __ldg(lp + l);
        float f2 = (q.x == 0.f && q.y == 0.f && q.z == 0.f && q.w == 0.f) ? 0.f : 1.f;
        float f  = flag1 * f2;
        float dxw = px - q.x;
        float dyw = py - q.y;
        float dX = (dxw * q.w + dyw * q.z) * 0.1f * f;
        float aX = fabsf(dX);
        if (aX < bestAbs) { bestAbs = aX; bestl = l; }   // strict < = first-min (jnp.argmin)
    }

    float4 mp  = dx_at(px, py, ps, pc, flag1, __ldg(lp + bestl));
    float4 el0 = dx_at(px, py, ps, pc, flag1, __ldg(lp + 0));
    float4 elL = dx_at(px, py, ps, pc, flag1, __ldg(lp + (LPTS - 1)));

    size_t pos = (size_t)row * MLANES + m;
    float4* ep = reinterpret_cast<float4*>(g_edge + pos * EDIM);   // 48B-aligned
    ep[0] = mp;
    ep[1] = el0;
    ep[2] = elL;
}

// ---------------------------------------------------------------------------
// Kernel 2: projection out[pos, e] = sum_d edge[pos,d] * W[e,d] + b[e]
// One warp per position (grid-stride). Lane t handles channels 4t..4t+3 as
// two packed f32x2 accumulators. Fully coalesced 512B float4 streaming stores.
// ---------------------------------------------------------------------------
__global__ void __launch_bounds__(256) proj_kernel(const float* __restrict__ W,
                                                   const float* __restrict__ bias,
                                                   float* __restrict__ out) {
    const int lane = threadIdx.x & 31;
    const int gw   = (blockIdx.x * blockDim.x + threadIdx.x) >> 5;
    const int nw   = (gridDim.x * blockDim.x) >> 5;
    const int e0   = lane * 4;

    // Pre-pack weights: w01[d] = {W[e0][d], W[e0+1][d]}, w23[d] = {W[e0+2][d], W[e0+3][d]}
    unsigned long long w01[EDIM], w23[EDIM];
#pragma unroll
    for (int d = 0; d < EDIM; d++) {
        float wa = __ldg(W + (e0 + 0) * EDIM + d);
        float wb = __ldg(W + (e0 + 1) * EDIM + d);
        float wc = __ldg(W + (e0 + 2) * EDIM + d);
        float wd = __ldg(W + (e0 + 3) * EDIM + d);
        asm("mov.b64 %0, {%1,%2};" : "=l"(w01[d]) : "f"(wa), "f"(wb));
        asm("mov.b64 %0, {%1,%2};" : "=l"(w23[d]) : "f"(wc), "f"(wd));
    }
    unsigned long long b01, b23;
    {
        float ba = __ldg(bias + e0 + 0);
        float bb = __ldg(bias + e0 + 1);
        float bc = __ldg(bias + e0 + 2);
        float bd = __ldg(bias + e0 + 3);
        asm("mov.b64 %0, {%1,%2};" : "=l"(b01) : "f"(ba), "f"(bb));
        asm("mov.b64 %0, {%1,%2};" : "=l"(b23) : "f"(bc), "f"(bd));
    }

    for (int pos = gw; pos < NPOS; pos += nw) {
        const float4* ep = reinterpret_cast<const float4*>(g_edge + (size_t)pos * EDIM);
        float4 v0 = __ldg(ep + 0);   // warp-uniform address -> broadcast
        float4 v1 = __ldg(ep + 1);
        float4 v2 = __ldg(ep + 2);
        float ed[EDIM] = { v0.x, v0.y, v0.z, v0.w,
                           v1.x, v1.y, v1.z, v1.w,
                           v2.x, v2.y, v2.z, v2.w };

        unsigned long long acc01 = b01, acc23 = b23;
#pragma unroll
        for (int d = 0; d < EDIM; d++) {
            unsigned long long ev;
            asm("mov.b64 %0, {%1,%1};" : "=l"(ev) : "f"(ed[d]));       // replicate scalar
            asm("fma.rn.f32x2 %0, %1, %2, %0;" : "+l"(acc01) : "l"(ev), "l"(w01[d]));
            asm("fma.rn.f32x2 %0, %1, %2, %0;" : "+l"(acc23) : "l"(ev), "l"(w23[d]));
        }

        float r0, r1, r2, r3;
        asm("mov.b64 {%0,%1}, %2;" : "=f"(r0), "=f"(r1) : "l"(acc01));
        asm("mov.b64 {%0,%1}, %2;" : "=f"(r2), "=f"(r3) : "l"(acc23));

        float4 o = make_float4(r0, r1, r2, r3);
        __stcs(reinterpret_cast<float4*>(out + (size_t)pos * NEMBD) + lane, o);
    }
}

// ---------------------------------------------------------------------------
// Launch: inputs in metadata order: agent, lane, W, b. Output fp32.
// ---------------------------------------------------------------------------
extern "C" void kernel_launch(void* const* d_in, const int* in_sizes, int n_in,
                              void* d_out, int out_size) {
    const float* agent = (const float*)d_in[0];
    const float* lane  = (const float*)d_in[1];
    const float* W     = (const float*)d_in[2];
    const float* bias  = (const float*)d_in[3];
    float* out = (float*)d_out;

    // Kernel 1: 8192 agent-rows, 4 rows/block of 256 threads -> 2048 blocks
    edge_kernel<<<2048, 256>>>(agent, lane);

    // Kernel 2: 2048 blocks x 256 threads = 16384 warps, 32 positions each
    proj_kernel<<<2048, 256>>>(W, bias, out);
}

// round 2
// speedup vs baseline: 1.5363x; 1.5363x over previous
#include <cuda_runtime.h>
#include <cstdint>

// Problem dims (fixed by the reference setup)
#define BATCH   8
#define NT      1024          // N*T = 32*32
#define MLANES  64            // M
#define LPTS    16            // L
#define NEMBD   128
#define EDIM    12
#define NPOS    (BATCH * NT * MLANES)   // 524288

// Scratch: edge tensor [NPOS][12] floats = 25 MB
__device__ float g_edge[(size_t)NPOS * EDIM];

// ---------------------------------------------------------------------------
// helpers: packed f32x2 ops (Blackwell)
// ---------------------------------------------------------------------------
__device__ __forceinline__ unsigned long long pack2(float a, float b) {
    unsigned long long r;
    asm("mov.b64 %0, {%1,%2};" : "=l"(r) : "f"(a), "f"(b));
    return r;
}
__device__ __forceinline__ void unpack2(unsigned long long v, float& a, float& b) {
    asm("mov.b64 {%0,%1}, %2;" : "=f"(a), "=f"(b) : "l"(v));
}
__device__ __forceinline__ void fma2(unsigned long long& acc,
                                     unsigned long long a, unsigned long long b) {
    asm("fma.rn.f32x2 %0, %1, %2, %0;" : "+l"(acc) : "l"(a), "l"(b));
}

// ---------------------------------------------------------------------------
// Kernel 1: compute edge features. One thread per (b, i, m).
// ---------------------------------------------------------------------------
__device__ __forceinline__ float4 dx_at(float px, float py, float ps, float pc,
                                        float flag1, float4 q) {
    float f2 = (q.x == 0.f && q.y == 0.f && q.z == 0.f && q.w == 0.f) ? 0.f : 1.f;
    float f  = flag1 * f2;
    float dxw = px - q.x;
    float dyw = py - q.y;
    float dX = (dxw * q.w + dyw * q.z) * 0.1f * f;   // delta_x / 10
    float dY = (-dxw * q.z + dyw * q.w) * 0.1f * f;  // delta_y / 10
    float ds = (ps * q.w - pc * q.z) * f;
    float dc = (pc * q.w + ps * q.z) * f;
    return make_float4(dX, dY, ds, dc);
}

__global__ void edge_kernel(const float* __restrict__ agent,
                            const float* __restrict__ lane) {
    int m   = threadIdx.x & 63;
    int g   = threadIdx.x >> 6;
    int row = blockIdx.x * 4 + g;          // (b*NT + i), 0..8191
    int b   = row >> 10;

    const float4* ap = reinterpret_cast<const float4*>(agent + (size_t)row * 8);
    float4 a0 = __ldg(ap + 0);
    float4 a1 = __ldg(ap + 1);
    float flag1 = (a0.x == 0.f && a0.y == 0.f && a0.z == 0.f && a0.w == 0.f &&
                   a1.x == 0.f && a1.y == 0.f && a1.z == 0.f && a1.w == 0.f) ? 0.f : 1.f;
    float px = a0.x, py = a0.y, ps = a0.w, pc = a1.x;

    const float4* lp = reinterpret_cast<const float4*>(lane + ((size_t)(b * MLANES + m)) * 64);

    float bestAbs = 3.4e38f;
    int   bestl   = 0;
#pragma unroll
    for (int l = 0; l < LPTS; l++) {
        float4 q = __ldg(lp + l);
        float f2 = (q.x == 0.f && q.y == 0.f && q.z == 0.f && q.w == 0.f) ? 0.f : 1.f;
        float f  = flag1 * f2;
        float dxw = px - q.x;
        float dyw = py - q.y;
        float dX = (dxw * q.w + dyw * q.z) * 0.1f * f;
        float aX = fabsf(dX);
        if (aX < bestAbs) { bestAbs = aX; bestl = l; }   // strict < = first-min (jnp.argmin)
    }

    float4 mp  = dx_at(px, py, ps, pc, flag1, __ldg(lp + bestl));
    float4 el0 = dx_at(px, py, ps, pc, flag1, __ldg(lp + 0));
    float4 elL = dx_at(px, py, ps, pc, flag1, __ldg(lp + (LPTS - 1)));

    size_t pos = (size_t)row * MLANES + m;
    float4* ep = reinterpret_cast<float4*>(g_edge + pos * EDIM);   // 48B-aligned
    ep[0] = mp;
    ep[1] = el0;
    ep[2] = elL;
}

// ---------------------------------------------------------------------------
// Kernel 2: projection out[pos, e] = sum_d edge[pos,d] * W[e,d] + b[e]
//
// Block = 128 threads = 4 warps. Tile = 32 positions (1.5 KB edge data in
// smem). Each block runs 8 consecutive tiles; the next tile is prefetched
// into registers (coalesced float4, high MLP) while the current one is
// computed, then STS'd. Each warp handles 8 positions; lane t owns channels
// 4t..4t+3. FMAs are d-pair-packed f32x2 (edge pairs read directly as 64-bit
// from smem) with a horizontal add in the epilogue; bias folded into acc init.
// ---------------------------------------------------------------------------
#define TPB        128
#define TILE_POS   32
#define POSW       8                      // positions per warp
#define TILES_PB   8                      // NPOS / TILE_POS / 2048
#define TILE_F4    ((TILE_POS * EDIM) / 4)  // 96 float4 per tile

__global__ void __launch_bounds__(TPB) proj_kernel(const float* __restrict__ W,
                                                   const float* __restrict__ bias,
                                                   float* __restrict__ out) {
    __shared__ __align__(16) float sedge[TILE_POS * EDIM];

    const int tid  = threadIdx.x;
    const int lane = tid & 31;
    const int warp = tid >> 5;
    const int e0   = lane * 4;

    // Weight pairs: wp[c][k] = {W[e0+c][2k], W[e0+c][2k+1]}  (48 regs)
    unsigned long long wp[4][6];
#pragma unroll
    for (int c = 0; c < 4; c++) {
        const float* wrow = W + (e0 + c) * EDIM;
#pragma unroll
        for (int k = 0; k < 6; k++)
            wp[c][k] = pack2(__ldg(wrow + 2 * k), __ldg(wrow + 2 * k + 1));
    }
    // acc init = {bias, 0}: even-d partial sums land in lo, odd-d in hi
    unsigned long long binit[4];
#pragma unroll
    for (int c = 0; c < 4; c++)
        binit[c] = pack2(__ldg(bias + e0 + c), 0.f);

    const size_t tile0 = (size_t)blockIdx.x * TILES_PB;
    const float4* esrc = reinterpret_cast<const float4*>(g_edge);
    const bool ldact = tid < TILE_F4;

    // Prefetch first tile
    float4 pref;
    if (ldact) pref = __ldg(esrc + tile0 * TILE_F4 + tid);

    for (int t = 0; t < TILES_PB; t++) {
        if (ldact) reinterpret_cast<float4*>(sedge)[tid] = pref;
        __syncthreads();

        // Prefetch next tile while computing this one
        if (t + 1 < TILES_PB && ldact)
            pref = __ldg(esrc + (tile0 + t + 1) * TILE_F4 + tid);

        const size_t gpos0 = (tile0 + t) * TILE_POS + warp * POSW;
        const int    sbase = warp * POSW;

#pragma unroll
        for (int p = 0; p < POSW; p++) {
            // 6 packed edge pairs, uniform smem address -> LDS broadcast
            const unsigned long long* er =
                reinterpret_cast<const unsigned long long*>(sedge + (sbase + p) * EDIM);
            unsigned long long ev[6];
#pragma unroll
            for (int k = 0; k < 6; k++) ev[k] = er[k];

            unsigned long long a0 = binit[0], a1 = binit[1],
                               a2 = binit[2], a3 = binit[3];
#pragma unroll
            for (int k = 0; k < 6; k++) {
                fma2(a0, ev[k], wp[0][k]);
                fma2(a1, ev[k], wp[1][k]);
                fma2(a2, ev[k], wp[2][k]);
                fma2(a3, ev[k], wp[3][k]);
            }

            float l0, h0, l1, h1, l2, h2, l3, h3;
            unpack2(a0, l0, h0); unpack2(a1, l1, h1);
            unpack2(a2, l2, h2); unpack2(a3, l3, h3);
            float4 o = make_float4(l0 + h0, l1 + h1, l2 + h2, l3 + h3);

            __stcs(reinterpret_cast<float4*>(out + (gpos0 + p) * NEMBD) + lane, o);
        }
        __syncthreads();
    }
}

// ---------------------------------------------------------------------------
// Launch: inputs in metadata order: agent, lane, W, b. Output fp32.
// ---------------------------------------------------------------------------
extern "C" void kernel_launch(void* const* d_in, const int* in_sizes, int n_in,
                              void* d_out, int out_size) {
    const float* agent = (const float*)d_in[0];
    const float* lane  = (const float*)d_in[1];
    const float* W     = (const float*)d_in[2];
    const float* bias  = (const float*)d_in[3];
    float* out = (float*)d_out;

    edge_kernel<<<2048, 256>>>(agent, lane);
    proj_kernel<<<2048, TPB>>>(W, bias, out);
}

// round 3
// speedup vs baseline: 2.3692x; 1.5422x over previous
#include <cuda_runtime.h>
#include <cstdint>

// Problem dims (fixed by the reference setup)
#define BATCH   8
#define NT      1024          // N*T
#define MLANES  64            // M
#define LPTS    16            // L
#define NEMBD   128
#define EDIM    12
#define NPOS    (BATCH * NT * MLANES)   // 524288

#define ROWS_PB 8             // agent rows per block
#define POS_PB  (ROWS_PB * MLANES)      // 512 positions per block
#define TPB     256

// ---------------------------------------------------------------------------
// packed f32x2 helpers (Blackwell)
// ---------------------------------------------------------------------------
__device__ __forceinline__ unsigned long long pack2(float a, float b) {
    unsigned long long r;
    asm("mov.b64 %0, {%1,%2};" : "=l"(r) : "f"(a), "f"(b));
    return r;
}
__device__ __forceinline__ void unpack2(unsigned long long v, float& a, float& b) {
    asm("mov.b64 {%0,%1}, %2;" : "=f"(a), "=f"(b) : "l"(v));
}
__device__ __forceinline__ void fma2(unsigned long long& acc,
                                     unsigned long long a, unsigned long long b) {
    asm("fma.rn.f32x2 %0, %1, %2, %0;" : "+l"(acc) : "l"(a), "l"(b));
}

__device__ __forceinline__ float4 dx_at(float px, float py, float ps, float pc,
                                        float flag1, float4 q) {
    float f2 = (q.x == 0.f && q.y == 0.f && q.z == 0.f && q.w == 0.f) ? 0.f : 1.f;
    float f  = flag1 * f2;
    float dxw = px - q.x;
    float dyw = py - q.y;
    float dX = (dxw * q.w + dyw * q.z) * 0.1f * f;   // delta_x / 10
    float dY = (-dxw * q.z + dyw * q.w) * 0.1f * f;  // delta_y / 10
    float ds = (ps * q.w - pc * q.z) * f;
    float dc = (pc * q.w + ps * q.z) * f;
    return make_float4(dX, dY, ds, dc);
}

// ---------------------------------------------------------------------------
// Fused kernel: edge features (smem-local) + projection.
// Block: 256 threads, 8 agent rows (same batch b) x 64 lanes = 512 positions.
//
// Phase 0: stage lane[b] transposed [l][m] (16KB) + 8 agent rows in smem.
// Phase A: 2 positions/thread; 16-pt argmin scan via conflict-free LDS.128;
//          write 12-float edge rows to smem.
// Phase B: warp-pair per position; lane owns 2 channels via d-pair-packed
//          f32x2 FMAs; bias folded into acc init; coalesced float2 stores.
// ---------------------------------------------------------------------------
__global__ void __launch_bounds__(TPB, 3)
fused_kernel(const float* __restrict__ agent,
             const float* __restrict__ lane,
             const float* __restrict__ W,
             const float* __restrict__ bias,
             float* __restrict__ out) {
    __shared__ __align__(16) float4 slane[LPTS * MLANES];    // [l][m], 16 KB
    __shared__ float sagent[ROWS_PB * 8];                    // 256 B
    __shared__ __align__(16) float sedge[POS_PB * EDIM];     // 24 KB

    const int tid  = threadIdx.x;
    const size_t row0 = (size_t)blockIdx.x * ROWS_PB;        // global agent row base
    const int b = (int)(row0 >> 10);

    // ---- Phase 0: stage lane (transposed) + agent rows ----
    const float4* lg = reinterpret_cast<const float4*>(lane) + (size_t)b * MLANES * LPTS;
#pragma unroll
    for (int k = 0; k < 4; k++) {
        int s = tid + k * 256;            // s = l*64 + m
        int l = s >> 6, m = s & 63;
        slane[s] = __ldg(lg + m * LPTS + l);   // scattered read (one-time, L2-hit)
    }
    if (tid < ROWS_PB * 8)
        sagent[tid] = __ldg(agent + row0 * 8 + tid);
    __syncthreads();

    // ---- Phase A: edge features into smem ----
#pragma unroll
    for (int it = 0; it < 2; it++) {
        int p = tid + it * 256;           // local position
        int r = p >> 6, m = p & 63;
        const float* ar = sagent + r * 8;
        float a0 = ar[0], a1 = ar[1], a2 = ar[2], a3 = ar[3];
        float a4 = ar[4], a5 = ar[5], a6 = ar[6], a7 = ar[7];
        float flag1 = (a0 == 0.f && a1 == 0.f && a2 == 0.f && a3 == 0.f &&
                       a4 == 0.f && a5 == 0.f && a6 == 0.f && a7 == 0.f) ? 0.f : 1.f;
        float px = a0, py = a1, ps = a3, pc = a4;

        float bestAbs = 3.4e38f;
        int   bestl   = 0;
#pragma unroll
        for (int l = 0; l < LPTS; l++) {
            float4 q = slane[l * MLANES + m];     // contiguous LDS.128, conflict-free
            float f2 = (q.x == 0.f && q.y == 0.f && q.z == 0.f && q.w == 0.f) ? 0.f : 1.f;
            float f01 = 0.1f * flag1 * f2;
            float dxw = px - q.x;
            float dyw = py - q.y;
            float aX = fabsf((dxw * q.w + dyw * q.z) * f01);
            if (aX < bestAbs) { bestAbs = aX; bestl = l; }   // strict < = first-min
        }

        float4 mp  = dx_at(px, py, ps, pc, flag1, slane[bestl * MLANES + m]);
        float4 el0 = dx_at(px, py, ps, pc, flag1, slane[0 * MLANES + m]);
        float4 elL = dx_at(px, py, ps, pc, flag1, slane[(LPTS - 1) * MLANES + m]);

        float4* ep = reinterpret_cast<float4*>(sedge + p * EDIM);   // 48B-aligned
        ep[0] = mp;
        ep[1] = el0;
        ep[2] = elL;
    }

    // ---- Phase B setup: per-lane weights for 2 channels (loaded while barrier drains) ----
    const int warp = tid >> 5;
    const int lid  = tid & 31;
    const int e0   = (warp & 1) * 64 + lid * 2;   // this lane's first channel

    unsigned long long wp0[6], wp1[6];
#pragma unroll
    for (int k = 0; k < 6; k++) {
        wp0[k] = pack2(__ldg(W + (e0 + 0) * EDIM + 2 * k), __ldg(W + (e0 + 0) * EDIM + 2 * k + 1));
        wp1[k] = pack2(__ldg(W + (e0 + 1) * EDIM + 2 * k), __ldg(W + (e0 + 1) * EDIM + 2 * k + 1));
    }
    const unsigned long long b0 = pack2(__ldg(bias + e0 + 0), 0.f);
    const unsigned long long b1 = pack2(__ldg(bias + e0 + 1), 0.f);

    __syncthreads();

    // ---- Phase B: projection. Warp-pair (w, w^1) covers one position. ----
    float* outbase = out + ((size_t)blockIdx.x * POS_PB) * NEMBD + e0;

#pragma unroll 2
    for (int p = (warp >> 1); p < POS_PB; p += 4) {
        const unsigned long long* er =
            reinterpret_cast<const unsigned long long*>(sedge + p * EDIM);
        unsigned long long ev[6];
#pragma unroll
        for (int k = 0; k < 6; k++) ev[k] = er[k];    // uniform LDS.64 -> broadcast

        unsigned long long acc0 = b0, acc1 = b1;
#pragma unroll
        for (int k = 0; k < 6; k++) {
            fma2(acc0, ev[k], wp0[k]);
            fma2(acc1, ev[k], wp1[k]);
        }

        float l0, h0, l1, h1;
        unpack2(acc0, l0, h0);
        unpack2(acc1, l1, h1);
        float2 o = make_float2(l0 + h0, l1 + h1);

        __stcs(reinterpret_cast<float2*>(outbase + (size_t)p * NEMBD), o);
    }
}

// ---------------------------------------------------------------------------
// Launch: inputs in metadata order: agent, lane, W, b. Output fp32.
// ---------------------------------------------------------------------------
extern "C" void kernel_launch(void* const* d_in, const int* in_sizes, int n_in,
                              void* d_out, int out_size) {
    const float* agent = (const float*)d_in[0];
    const float* lane  = (const float*)d_in[1];
    const float* W     = (const float*)d_in[2];
    const float* bias  = (const float*)d_in[3];
    float* out = (float*)d_out;

    // 8192 agent rows / 8 rows per block = 1024 blocks
    fused_kernel<<<NPOS / POS_PB, TPB>>>(agent, lane, W, bias, out);
}